// round 11
// baseline (speedup 1.0000x reference)
#include <cuda_runtime.h>
#include <math.h>

// Problem shape (fixed by the reference)
#define B 32
#define S 4096
#define H 768            // 768 floats = 6 float4 per lane across a warp
#define CHUNKS 9         // CTAs per batch -> 288 CTAs total (single wave)
#define WARPS 8          // warps per CTA
#define NPART (B * CHUNKS)                   // 288 CTA-level partials

// Scratch for CTA partials + per-batch arrival counters (allocation-free).
__device__ float g_pm[NPART];
__device__ float g_pl[NPART];
__device__ float g_pacc[(size_t)NPART * H];   // 884 KB (L2-resident)
__device__ unsigned int g_count[B] = {};      // reset by last CTA per replay

// ---------------------------------------------------------------------------
// Fused single-query attention, single wave, 3-deep register row pipeline:
// two rows (6 KB/warp) always in flight -> MLP_p1 = 12 per warp.
// q lives in shared memory to stay under the 128-reg/thread budget.
// ---------------------------------------------------------------------------
__global__ __launch_bounds__(256, 2)
void attn_fused(const float* __restrict__ hidden, const float* __restrict__ q,
                float* __restrict__ out)
{
    const int bx    = blockIdx.x;            // 0..287
    const int b     = bx / CHUNKS;           // batch
    const int chunk = bx % CHUNKS;
    const int wid   = threadIdx.x >> 5;
    const int lane  = threadIdx.x & 31;

    __shared__ float s_q[H];                 // 3 KB
    __shared__ float s_m[WARPS];
    __shared__ float s_l[WARPS];
    __shared__ float s_acc[WARPS][H];        // 24 KB
    __shared__ unsigned int s_ticket;

    // stage q into smem (3 floats per thread)
#pragma unroll
    for (int j = 0; j < 3; j++) s_q[threadIdx.x + j * 256] = q[threadIdx.x + j * 256];
    __syncthreads();
    const float4* sq4 = (const float4*)s_q;

    const float* base = hidden + (size_t)b * S * H;

    // chunk row range within this batch, then warp sub-range (balanced splits)
    const int c0 = (chunk * S) / CHUNKS;
    const int c1 = ((chunk + 1) * S) / CHUNKS;
    const int w0 = c0 + (wid * (c1 - c0)) / WARPS;
    const int w1 = c0 + ((wid + 1) * (c1 - c0)) / WARPS;
    const int nrows = w1 - w0;               // ~56-57 (always >= 3)

    float4 acc[6];
#pragma unroll
    for (int i = 0; i < 6; i++) acc[i] = make_float4(0.f, 0.f, 0.f, 0.f);
    float m = -INFINITY;
    float l = 0.f;

    float4 xa[6], xb[6], xc[6];

    // prefetch row (clamped to warp range: duplicate loads are harmless)
    #define LOADROW(buf, row) do {                                          \
        int rl_ = (row); if (rl_ > w1 - 1) rl_ = w1 - 1;                    \
        const float4* rp_ = (const float4*)(base + (size_t)rl_ * H);        \
        _Pragma("unroll")                                                   \
        for (int i_ = 0; i_ < 6; i_++) buf[i_] = rp_[i_ * 32 + lane];       \
    } while (0)

    // consume one resident row: dot (q from smem), shuffle-reduce,
    // online-softmax update, weighted accumulate
    #define CONSUME(buf) do {                                               \
        float d0_ = 0.f, d1_ = 0.f;                                         \
        _Pragma("unroll")                                                   \
        for (int i_ = 0; i_ < 3; i_++) {                                    \
            const float4 qq_ = sq4[i_ * 32 + lane];                         \
            d0_ = fmaf(buf[i_].x, qq_.x, d0_);                              \
            d0_ = fmaf(buf[i_].y, qq_.y, d0_);                              \
            d0_ = fmaf(buf[i_].z, qq_.z, d0_);                              \
            d0_ = fmaf(buf[i_].w, qq_.w, d0_);                              \
        }                                                                   \
        _Pragma("unroll")                                                   \
        for (int i_ = 3; i_ < 6; i_++) {                                    \
            const float4 qq_ = sq4[i_ * 32 + lane];                         \
            d1_ = fmaf(buf[i_].x, qq_.x, d1_);                              \
            d1_ = fmaf(buf[i_].y, qq_.y, d1_);                              \
            d1_ = fmaf(buf[i_].z, qq_.z, d1_);                              \
            d1_ = fmaf(buf[i_].w, qq_.w, d1_);                              \
        }                                                                   \
        float d_ = d0_ + d1_;                                               \
        _Pragma("unroll")                                                   \
        for (int o_ = 16; o_ > 0; o_ >>= 1)                                 \
            d_ += __shfl_xor_sync(0xffffffffu, d_, o_);                     \
        if (d_ > m) {                                                       \
            const float sc_ = __expf(m - d_);                               \
            l *= sc_;                                                       \
            _Pragma("unroll")                                               \
            for (int i_ = 0; i_ < 6; i_++) {                                \
                acc[i_].x *= sc_; acc[i_].y *= sc_;                         \
                acc[i_].z *= sc_; acc[i_].w *= sc_;                         \
            }                                                               \
            m = d_;                                                         \
        }                                                                   \
        const float w_ = __expf(d_ - m);                                    \
        l += w_;                                                            \
        _Pragma("unroll")                                                   \
        for (int i_ = 0; i_ < 6; i_++) {                                    \
            acc[i_].x = fmaf(w_, buf[i_].x, acc[i_].x);                     \
            acc[i_].y = fmaf(w_, buf[i_].y, acc[i_].y);                     \
            acc[i_].z = fmaf(w_, buf[i_].z, acc[i_].z);                     \
            acc[i_].w = fmaf(w_, buf[i_].w, acc[i_].w);                     \
        }                                                                   \
    } while (0)

    // prologue: 3 rows in flight
    LOADROW(xa, w0);
    LOADROW(xb, w0 + 1);
    LOADROW(xc, w0 + 2);

    int r = 0;
    // steady state: always 2 rows ahead in flight (MLP_p1 = 12)
    while (r + 3 <= nrows) {
        CONSUME(xa); LOADROW(xa, w0 + r + 3);
        CONSUME(xb); LOADROW(xb, w0 + r + 4);
        CONSUME(xc); LOADROW(xc, w0 + r + 5);
        r += 3;
    }
    // tail: 0..2 rows left resident (clamped prefetches hold duplicates)
    if (r     < nrows) CONSUME(xa);
    if (r + 1 < nrows) CONSUME(xb);
    if (r + 2 < nrows) CONSUME(xc);

    // ---- CTA-level merge of the 8 warp partials through shared memory ----
    if (lane == 0) { s_m[wid] = m; s_l[wid] = l; }
    {
        float4* sa = (float4*)s_acc[wid];
#pragma unroll
        for (int i = 0; i < 6; i++) sa[i * 32 + lane] = acc[i];
    }
    __syncthreads();

    float M = s_m[0];
#pragma unroll
    for (int w = 1; w < WARPS; w++) M = fmaxf(M, s_m[w]);

    // each thread owns 3 h-values: conflict-free LDS, coalesced STG
    float* pa = g_pacc + (size_t)bx * H;
#pragma unroll
    for (int j = 0; j < 3; j++) {
        const int h = threadIdx.x + j * 256;
        float rr = 0.f;
#pragma unroll
        for (int w = 0; w < WARPS; w++)
            rr = fmaf(__expf(s_m[w] - M), s_acc[w][h], rr);
        pa[h] = rr;
    }
    if (threadIdx.x == 0) {
        float L = 0.f;
#pragma unroll
        for (int w = 0; w < WARPS; w++) L = fmaf(__expf(s_m[w] - M), s_l[w], L);
        g_pm[bx] = M;
        g_pl[bx] = L;
    }

    // ---- last CTA of this batch combines the 9 partials ----
    if (threadIdx.x == 0) {
        __threadfence();                      // partials visible before count
        s_ticket = atomicAdd(&g_count[b], 1u);
    }
    __syncthreads();
    if (s_ticket != CHUNKS - 1) return;

    __threadfence();                          // acquire: see all partials

    const int p0 = b * CHUNKS;
    float GM = -INFINITY;
#pragma unroll
    for (int c = 0; c < CHUNKS; c++) GM = fmaxf(GM, g_pm[p0 + c]);

    float r0 = 0.f, r1 = 0.f, r2 = 0.f, L = 0.f;
    const int h0 = threadIdx.x;
#pragma unroll
    for (int c = 0; c < CHUNKS; c++) {
        const float w = __expf(g_pm[p0 + c] - GM);
        const float* pc = g_pacc + (size_t)(p0 + c) * H;
        L  = fmaf(w, g_pl[p0 + c], L);
        r0 = fmaf(w, pc[h0],       r0);
        r1 = fmaf(w, pc[h0 + 256], r1);
        r2 = fmaf(w, pc[h0 + 512], r2);
    }
    const float invL = 1.f / L;
    float* ob = out + b * H;
    ob[h0]       = r0 * invL;
    ob[h0 + 256] = r1 * invL;
    ob[h0 + 512] = r2 * invL;

    if (threadIdx.x == 0) g_count[b] = 0;     // reset for next graph replay
}

extern "C" void kernel_launch(void* const* d_in, const int* in_sizes, int n_in,
                              void* d_out, int out_size)
{
    const float* hidden = (const float*)d_in[0];   // [32, 4096, 768] f32
    const float* querys = (const float*)d_in[1];   // [1, 768] f32
    float* out = (float*)d_out;                    // [32, 768] f32

    attn_fused<<<B * CHUNKS, 256>>>(hidden, querys, out);
}

// round 12
// speedup vs baseline: 1.2631x; 1.2631x over previous
#include <cuda_runtime.h>
#include <math.h>

// Problem shape (fixed by the reference)
#define B 32
#define S 4096
#define H 768            // 768 floats = 6 float4 per lane across a warp
#define CHUNKS 9         // CTAs per batch -> 288 CTAs total (single wave)
#define WARPS 8          // warps per CTA
#define NPART (B * CHUNKS)                   // 288 CTA-level partials

// Scratch for CTA partials + per-batch arrival counters (allocation-free).
// g_count is statically zero-initialized; the last CTA of each batch resets
// its counter, so every graph replay starts from identical state.
__device__ float g_pm[NPART];
__device__ float g_pl[NPART];
__device__ float g_pacc[(size_t)NPART * H];   // 884 KB (L2-resident)
__device__ unsigned int g_count[B] = {};

// ---------------------------------------------------------------------------
// Fused single-query attention, single wave (R10 structure):
//   - register double-buffered row stream (x / xn)
//   - q in shared memory (frees ~20 regs -> better LDG hoisting, no spills)
//   - online softmax + weighted accumulate, row held in registers
//   - CTA smem merge of 8 warp partials
//   - last CTA per batch combines the 9 partials
// ---------------------------------------------------------------------------
__global__ __launch_bounds__(256, 2)
void attn_fused(const float* __restrict__ hidden, const float* __restrict__ q,
                float* __restrict__ out)
{
    const int bx    = blockIdx.x;            // 0..287
    const int b     = bx / CHUNKS;           // batch
    const int chunk = bx % CHUNKS;
    const int wid   = threadIdx.x >> 5;
    const int lane  = threadIdx.x & 31;

    __shared__ float s_q[H];                 // 3 KB
    __shared__ float s_m[WARPS];
    __shared__ float s_l[WARPS];
    __shared__ float s_acc[WARPS][H];        // 24 KB
    __shared__ unsigned int s_ticket;

    // stage q into smem (3 floats per thread)
#pragma unroll
    for (int j = 0; j < 3; j++)
        s_q[threadIdx.x + j * 256] = q[threadIdx.x + j * 256];
    __syncthreads();
    const float4* sq4 = (const float4*)s_q;

    const float* base = hidden + (size_t)b * S * H;

    // chunk row range within this batch, then warp sub-range (balanced splits)
    const int c0 = (chunk * S) / CHUNKS;
    const int c1 = ((chunk + 1) * S) / CHUNKS;
    const int w0 = c0 + (wid * (c1 - c0)) / WARPS;
    const int w1 = c0 + ((wid + 1) * (c1 - c0)) / WARPS;
    const int nrows = w1 - w0;               // ~56-57

    float4 acc[6];
#pragma unroll
    for (int i = 0; i < 6; i++) acc[i] = make_float4(0.f, 0.f, 0.f, 0.f);
    float m = -INFINITY;
    float l = 0.f;

    // prefetch first row
    float4 x[6], xn[6];
    {
        const float4* rp = (const float4*)(base + (size_t)w0 * H);
#pragma unroll
        for (int i = 0; i < 6; i++) x[i] = rp[i * 32 + lane];
    }

    for (int r = 0; r < nrows; r++) {
        // prefetch next row (independent of the softmax chain below)
        if (r + 1 < nrows) {
            const float4* rp = (const float4*)(base + (size_t)(w0 + r + 1) * H);
#pragma unroll
            for (int i = 0; i < 6; i++) xn[i] = rp[i * 32 + lane];
        }

        // dot(hidden_row, q) — two independent FMA chains
        float d0 = 0.f, d1 = 0.f;
#pragma unroll
        for (int i = 0; i < 3; i++) {
            const float4 qq = sq4[i * 32 + lane];
            d0 = fmaf(x[i].x, qq.x, d0);
            d0 = fmaf(x[i].y, qq.y, d0);
            d0 = fmaf(x[i].z, qq.z, d0);
            d0 = fmaf(x[i].w, qq.w, d0);
        }
#pragma unroll
        for (int i = 3; i < 6; i++) {
            const float4 qq = sq4[i * 32 + lane];
            d1 = fmaf(x[i].x, qq.x, d1);
            d1 = fmaf(x[i].y, qq.y, d1);
            d1 = fmaf(x[i].z, qq.z, d1);
            d1 = fmaf(x[i].w, qq.w, d1);
        }
        float d = d0 + d1;
#pragma unroll
        for (int o = 16; o > 0; o >>= 1)
            d += __shfl_xor_sync(0xffffffffu, d, o);

        // online softmax update (warp-uniform m, l)
        if (d > m) {
            const float sc = __expf(m - d);   // exp(-inf) = 0 on first row
            l *= sc;
#pragma unroll
            for (int i = 0; i < 6; i++) {
                acc[i].x *= sc; acc[i].y *= sc; acc[i].z *= sc; acc[i].w *= sc;
            }
            m = d;
        }
        const float w = __expf(d - m);
        l += w;
#pragma unroll
        for (int i = 0; i < 6; i++) {
            acc[i].x = fmaf(w, x[i].x, acc[i].x);
            acc[i].y = fmaf(w, x[i].y, acc[i].y);
            acc[i].z = fmaf(w, x[i].z, acc[i].z);
            acc[i].w = fmaf(w, x[i].w, acc[i].w);
        }

#pragma unroll
        for (int i = 0; i < 6; i++) x[i] = xn[i];
    }

    // ---- CTA-level merge of the 8 warp partials through shared memory ----
    if (lane == 0) { s_m[wid] = m; s_l[wid] = l; }
    {
        float4* sa = (float4*)s_acc[wid];
#pragma unroll
        for (int i = 0; i < 6; i++) sa[i * 32 + lane] = acc[i];
    }
    __syncthreads();

    float M = s_m[0];
#pragma unroll
    for (int w = 1; w < WARPS; w++) M = fmaxf(M, s_m[w]);

    // each thread owns 3 h-values: conflict-free LDS, coalesced STG
    float* pa = g_pacc + (size_t)bx * H;
#pragma unroll
    for (int j = 0; j < 3; j++) {
        const int h = threadIdx.x + j * 256;
        float rr = 0.f;
#pragma unroll
        for (int w = 0; w < WARPS; w++)
            rr = fmaf(__expf(s_m[w] - M), s_acc[w][h], rr);
        pa[h] = rr;
    }
    if (threadIdx.x == 0) {
        float L = 0.f;
#pragma unroll
        for (int w = 0; w < WARPS; w++) L = fmaf(__expf(s_m[w] - M), s_l[w], L);
        g_pm[bx] = M;
        g_pl[bx] = L;
    }

    // ---- last CTA of this batch combines the 9 partials ----
    if (threadIdx.x == 0) {
        __threadfence();                      // partials visible before count
        s_ticket = atomicAdd(&g_count[b], 1u);
    }
    __syncthreads();
    if (s_ticket != CHUNKS - 1) return;

    __threadfence();                          // acquire: see all partials

    const int p0 = b * CHUNKS;
    float GM = -INFINITY;
#pragma unroll
    for (int c = 0; c < CHUNKS; c++) GM = fmaxf(GM, g_pm[p0 + c]);

    float r0 = 0.f, r1 = 0.f, r2 = 0.f, L = 0.f;
    const int h0 = threadIdx.x;
#pragma unroll
    for (int c = 0; c < CHUNKS; c++) {
        const float w = __expf(g_pm[p0 + c] - GM);
        const float* pc = g_pacc + (size_t)(p0 + c) * H;
        L  = fmaf(w, g_pl[p0 + c], L);
        r0 = fmaf(w, pc[h0],       r0);
        r1 = fmaf(w, pc[h0 + 256], r1);
        r2 = fmaf(w, pc[h0 + 512], r2);
    }
    const float invL = 1.f / L;
    float* ob = out + b * H;
    ob[h0]       = r0 * invL;
    ob[h0 + 256] = r1 * invL;
    ob[h0 + 512] = r2 * invL;

    if (threadIdx.x == 0) g_count[b] = 0;     // reset for next graph replay
}

extern "C" void kernel_launch(void* const* d_in, const int* in_sizes, int n_in,
                              void* d_out, int out_size)
{
    const float* hidden = (const float*)d_in[0];   // [32, 4096, 768] f32
    const float* querys = (const float*)d_in[1];   // [1, 768] f32
    float* out = (float*)d_out;                    // [32, 768] f32

    attn_fused<<<B * CHUNKS, 256>>>(hidden, querys, out);
}